// round 14
// baseline (speedup 1.0000x reference)
#include <cuda_runtime.h>

#define NTAGS    1024
#define NCTA     128
#define TPB      256
#define WARPS    8
#define ROWS     8           // tag rows per CTA
#define TSTEPS   65536
#define SPIN_CAP (1u << 20)  // watchdog (~0.25s worst case), unreachable normally
#define VCAP     (1u << 16)

// Persistent device state.
// g_ab: {f32 alpha, u32 tag} packed in 8B -> one b64 load observes
//       value+readiness atomically (no fences needed anywhere).
// g_rep: one tag per producer CTA, contiguous (4 lines) -> cheap polling.
__device__ __align__(16) unsigned long long g_ab[2][NTAGS];
__device__ __align__(16) unsigned           g_rep[2][NCTA];
__device__ unsigned g_gen = 0;   // bumped once per launch (replay-safe tags)

__device__ __forceinline__ unsigned long long ld_rlx64(const unsigned long long* p) {
    unsigned long long v;
    asm volatile("ld.relaxed.gpu.global.b64 %0, [%1];" : "=l"(v) : "l"(p));
    return v;
}
__device__ __forceinline__ void st_rlx64(unsigned long long* p, unsigned long long v) {
    asm volatile("st.relaxed.gpu.global.b64 [%0], %1;" :: "l"(p), "l"(v) : "memory");
}
__device__ __forceinline__ unsigned ld_rlx32(const unsigned* p) {
    unsigned v;
    asm volatile("ld.relaxed.gpu.global.u32 %0, [%1];" : "=r"(v) : "l"(p));
    return v;
}
__device__ __forceinline__ void st_rlx32(unsigned* p, unsigned v) {
    asm volatile("st.relaxed.gpu.global.u32 [%0], %1;" :: "l"(p), "r"(v) : "memory");
}
__device__ __forceinline__ unsigned long long pack_av(float a, unsigned tag) {
    return ((unsigned long long)tag << 32) | (unsigned long long)__float_as_uint(a);
}
__device__ __forceinline__ float    val_of(unsigned long long q) { return __uint_as_float((unsigned)q); }
__device__ __forceinline__ unsigned tag_of(unsigned long long q) { return (unsigned)(q >> 32); }

// Register-halving butterfly (validated in R2): sums p[0..7] across the warp
// in 9 shfls. On return lane<8 holds the full 32-lane sum of row
// row_of_lane(lane) = 4*(lane&1) + 2*((lane>>1)&1) + ((lane>>2)&1).
__device__ __forceinline__ float warp_sum8(float p[8], int lane) {
    #pragma unroll
    for (int i = 0; i < 4; i++) {
        float lo = p[i], hi = p[i + 4];
        float mine  = (lane & 1) ? lo : hi;
        float other = __shfl_xor_sync(0xffffffffu, mine, 1);
        p[i] = ((lane & 1) ? hi : lo) + other;
    }
    #pragma unroll
    for (int i = 0; i < 2; i++) {
        float lo = p[i], hi = p[i + 2];
        float mine  = (lane & 2) ? lo : hi;
        float other = __shfl_xor_sync(0xffffffffu, mine, 2);
        p[i] = ((lane & 2) ? hi : lo) + other;
    }
    {
        float lo = p[0], hi = p[1];
        float mine  = (lane & 4) ? lo : hi;
        float other = __shfl_xor_sync(0xffffffffu, mine, 4);
        p[0] = ((lane & 4) ? hi : lo) + other;
    }
    p[0] += __shfl_xor_sync(0xffffffffu, p[0], 8);
    p[0] += __shfl_xor_sync(0xffffffffu, p[0], 16);
    return p[0];
}
__device__ __forceinline__ int row_of_lane(int lane) {
    return 4 * (lane & 1) + 2 * ((lane >> 1) & 1) + ((lane >> 2) & 1);
}

__global__ void __launch_bounds__(TPB, 1)
crf_kernel(const float* __restrict__ unary,
           const float* __restrict__ trans,
           const int*   __restrict__ start_p,
           const int*   __restrict__ end_p,
           float*       __restrict__ out)
{
    const int tid  = threadIdx.x;
    const int lane = tid & 31;
    const int w    = tid >> 5;           // 8 warps
    const int cta  = blockIdx.x;
    const int base = cta * ROWS;         // first tag row owned by this CTA

    __shared__ float s_p[WARPS][ROWS];   // per-warp partial row sums
    __shared__ float s_a[2][ROWS];       // own alpha rows, double-buffered
    __shared__ int   s_bail;

    const unsigned gen = g_gen;          // stream-ordered across graph replays
    // tag(step s) = gen*65536 + s + 1   (never 0, unique across replays)

    if (tid == 0) s_bail = 0;

    // ---- E tile in registers: thread owns cols [4*tid, 4*tid+4) for all
    // 8 of this CTA's rows (coalesced float4 loads).
    float E[ROWS][4];
    #pragma unroll
    for (int r = 0; r < ROWS; r++) {
        const float4 tr = *reinterpret_cast<const float4*>(
            &trans[(size_t)(base + r) * NTAGS + 4 * tid]);
        E[r][0] = __expf(tr.x); E[r][1] = __expf(tr.y);
        E[r][2] = __expf(tr.z); E[r][3] = __expf(tr.w);
    }

    // ---- Step 0: alpha_0[i] = trans[i, start] + u_0[i] ------------------
    float u_next = 0.0f;                 // threads 0..7: next step's unary for row base+tid
    {
        const int sidx = *start_p;
        if (tid < ROWS) {
            const float a0 = __ldg(&trans[(size_t)(base + tid) * NTAGS + sidx])
                           + __ldg(&unary[base + tid]);
            s_a[0][tid] = a0;
            s_a[1][tid] = a0;            // stands in for alpha_{-1} at t=1,2
            st_rlx64(&g_ab[0][base + tid], pack_av(a0, gen * 65536u + 1u));
            u_next = __ldcs(&unary[(size_t)NTAGS + base + tid]);
        }
        if (w == 0) {
            __syncwarp();                // row stores issued before rep publish
            if (lane == 0) st_rlx32(&g_rep[0][cta], gen * 65536u + 1u);
        }
    }
    __syncthreads();

    // ---- Main scan ------------------------------------------------------
    for (int t = 1; t < TSTEPS; t++) {
        const int pb = (t - 1) & 1;      // buffer holding alpha_{t-1}
        const int b  = t & 1;

        // exp-offset from alpha_{t-2}; fmax only, no MUFU on this path.
        float mm = s_a[b][0];
        #pragma unroll
        for (int r = 1; r < ROWS; r++) mm = fmaxf(mm, s_a[b][r]);
        const float m = mm + 30.0f;      // covers 2 steps of drift + spread

        const unsigned want = gen * 65536u + (unsigned)t;  // tag of step t-1

        // SPECULATIVE loads of this thread's 4 columns (32B coalesced),
        // issued before detection; usually fresh by bar1.
        const unsigned long long* src = g_ab[pb] + 4 * tid;
        unsigned long long q0 = ld_rlx64(src + 0);
        unsigned long long q1 = ld_rlx64(src + 1);
        unsigned long long q2 = ld_rlx64(src + 2);
        unsigned long long q3 = ld_rlx64(src + 3);

        // NARROW poll: warp 0 spins on the 128 contiguous rep tags (4 lines).
        if (w == 0) {
            unsigned spins = 0;
            for (;;) {
                const unsigned r0 = ld_rlx32(&g_rep[pb][lane]);
                const unsigned r1 = ld_rlx32(&g_rep[pb][lane + 32]);
                const unsigned r2 = ld_rlx32(&g_rep[pb][lane + 64]);
                const unsigned r3 = ld_rlx32(&g_rep[pb][lane + 96]);
                const bool ok = ((r0 ^ want) | (r1 ^ want) |
                                 (r2 ^ want) | (r3 ^ want)) == 0u;
                if (__all_sync(0xffffffffu, ok)) break;
                if (++spins > SPIN_CAP) { s_bail = 1; break; }
            }
        }
        __syncthreads();                 // bar1: detection done; bail broadcast
        if (s_bail) break;

        // Verify speculative loads; retry only stale stragglers.
        {
            unsigned vs = 0;
            while (((tag_of(q0) ^ want) | (tag_of(q1) ^ want) |
                    (tag_of(q2) ^ want) | (tag_of(q3) ^ want)) != 0u) {
                q0 = ld_rlx64(src + 0); q1 = ld_rlx64(src + 1);
                q2 = ld_rlx64(src + 2); q3 = ld_rlx64(src + 3);
                if (++vs > VCAP) break;
            }
        }

        // exp in registers -- no smem broadcast, no crossbar stage.
        const float x0 = __expf(val_of(q0) - m);
        const float x1 = __expf(val_of(q1) - m);
        const float x2 = __expf(val_of(q2) - m);
        const float x3 = __expf(val_of(q3) - m);

        // 32 FMAs: partial dot of all 8 rows over this thread's 4 columns.
        float p[ROWS];
        #pragma unroll
        for (int r = 0; r < ROWS; r++)
            p[r] = fmaf(E[r][3], x3,
                   fmaf(E[r][2], x2,
                   fmaf(E[r][1], x1, E[r][0] * x0)));

        const float psum = warp_sum8(p, lane);   // 9 shfls, 5 dependent
        if (lane < ROWS) s_p[w][row_of_lane(lane)] = psum;
        __syncthreads();                 // bar2: partials staged

        // Final stage: warp 0, lane r sums 8 partials of row base+r,
        // publishes alpha. Rep follows all row stores via syncwarp.
        if (w == 0) {
            if (lane < ROWS) {
                float s = s_p[0][lane];
                #pragma unroll
                for (int w2 = 1; w2 < WARPS; w2++) s += s_p[w2][lane];
                const float alpha = __logf(s) + m + u_next;
                s_a[b][lane] = alpha;
                st_rlx64(&g_ab[b][base + lane], pack_av(alpha, want + 1u));
                const int tn = (t + 1 < TSTEPS) ? t + 1 : t;
                u_next = __ldcs(&unary[(size_t)tn * NTAGS + base + lane]);
            }
            __syncwarp();
            if (lane == 0) st_rlx32(&g_rep[b][cta], want + 1u);
        }
        // next iteration's bar1 provides all remaining smem ordering
    }

    // ---- Terminal logsumexp (CTA 0) -------------------------------------
    if (cta == 0) {
        const unsigned want = gen * 65536u + (unsigned)TSTEPS; // tag of step T-1
        const unsigned long long* src = g_ab[(TSTEPS - 1) & 1] + 4 * tid;
        unsigned long long q0 = ld_rlx64(src + 0);
        unsigned long long q1 = ld_rlx64(src + 1);
        unsigned long long q2 = ld_rlx64(src + 2);
        unsigned long long q3 = ld_rlx64(src + 3);
        {
            unsigned vs = 0;
            while (((tag_of(q0) ^ want) | (tag_of(q1) ^ want) |
                    (tag_of(q2) ^ want) | (tag_of(q3) ^ want)) != 0u) {
                q0 = ld_rlx64(src + 0); q1 = ld_rlx64(src + 1);
                q2 = ld_rlx64(src + 2); q3 = ld_rlx64(src + 3);
                if (++vs > VCAP) break;
            }
        }

        const int eidx = *end_p;
        const float4 tr = *reinterpret_cast<const float4*>(
            &trans[(size_t)eidx * NTAGS + 4 * tid]);
        const float x0 = val_of(q0) + tr.x;
        const float x1 = val_of(q1) + tr.y;
        const float x2 = val_of(q2) + tr.z;
        const float x3 = val_of(q3) + tr.w;

        float mx = fmaxf(fmaxf(x0, x1), fmaxf(x2, x3));
        #pragma unroll
        for (int msk = 16; msk >= 1; msk >>= 1)
            mx = fmaxf(mx, __shfl_xor_sync(0xffffffffu, mx, msk));
        if (lane == 0) s_p[0][w] = mx;   // 8 slots
        __syncthreads();
        float M = s_p[0][0];
        #pragma unroll
        for (int w2 = 1; w2 < WARPS; w2++) M = fmaxf(M, s_p[0][w2]);

        float s = __expf(x0 - M) + __expf(x1 - M) + __expf(x2 - M) + __expf(x3 - M);
        #pragma unroll
        for (int msk = 16; msk >= 1; msk >>= 1)
            s += __shfl_xor_sync(0xffffffffu, s, msk);
        if (lane == 0) s_p[1][w] = s;
        __syncthreads();

        if (tid == 0) {
            float Ssum = s_p[1][0];
            #pragma unroll
            for (int w2 = 1; w2 < WARPS; w2++) Ssum += s_p[1][w2];
            out[0] = __logf(Ssum) + M;
            g_gen = gen + 1;             // version tags for the next replay
        }
    }
}

extern "C" void kernel_launch(void* const* d_in, const int* in_sizes, int n_in,
                              void* d_out, int out_size)
{
    const float* unary = (const float*)d_in[0];   // [65536, 1024] f32
    const float* trans = (const float*)d_in[1];   // [1024, 1024]  f32
    const int*   sidx  = (const int*)d_in[2];     // scalar
    const int*   eidx  = (const int*)d_in[3];     // scalar
    float*       out   = (float*)d_out;           // scalar f32

    crf_kernel<<<NCTA, TPB>>>(unary, trans, sidx, eidx, out);
}

// round 16
// speedup vs baseline: 1.2816x; 1.2816x over previous
#include <cuda_runtime.h>

#define NTAGS    1024
#define NCTA     128
#define TPB      256
#define WARPS    8
#define NREP     8           // replicas of the alpha vector; CTA c polls replica c&7
#define TSTEPS   65536
#define SPIN_CAP (1u << 18)  // watchdog (~60ms worst case grid-wide), unreachable normally
#define VCAP     (1u << 16)

// Persistent device state: 8 replicas of the tagged alpha vector, double-buffered.
// Entry = {f32 alpha, u32 tag}; one b64 load observes value+readiness atomically,
// so detection IS the data load and no fences are needed anywhere.
__device__ __align__(16) unsigned long long g_abR[NREP][2][NTAGS];   // 128 KB
__device__ unsigned g_gen = 0;   // bumped once per launch (replay-safe tags)

__device__ __forceinline__ unsigned long long ld_rlx64(const unsigned long long* p) {
    unsigned long long v;
    asm volatile("ld.relaxed.gpu.global.b64 %0, [%1];" : "=l"(v) : "l"(p));
    return v;
}
__device__ __forceinline__ void st_rlx64(unsigned long long* p, unsigned long long v) {
    asm volatile("st.relaxed.gpu.global.b64 [%0], %1;" :: "l"(p), "l"(v) : "memory");
}
__device__ __forceinline__ unsigned long long pack_av(float a, unsigned tag) {
    return ((unsigned long long)tag << 32) | (unsigned long long)__float_as_uint(a);
}
__device__ __forceinline__ float    val_of(unsigned long long q) { return __uint_as_float((unsigned)q); }
__device__ __forceinline__ unsigned tag_of(unsigned long long q) { return (unsigned)(q >> 32); }

__global__ void __launch_bounds__(TPB, 1)
crf_kernel(const float* __restrict__ unary,
           const float* __restrict__ trans,
           const int*   __restrict__ start_p,
           const int*   __restrict__ end_p,
           float*       __restrict__ out)
{
    const int tid  = threadIdx.x;
    const int lane = tid & 31;
    const int w    = tid >> 5;           // 8 warps
    const int cta  = blockIdx.x;
    const int row  = cta * WARPS + w;    // this warp's tag row

    __shared__ float sx[2][NTAGS];       // exp(alpha - m), double-buffered by t&1
    __shared__ float s_a[2][WARPS];      // own alpha rows (for the stale exp offset)
    __shared__ int   s_bail;

    const unsigned gen = g_gen;          // stream-ordered across graph replays
    // tag(step s) = gen*65536 + s + 1   (never 0, unique across replays)

    if (tid == 0) s_bail = 0;

    // ---- E row in registers: warp w owns row `row`, lane owns cols {lane+32k}
    float E[32];
    #pragma unroll
    for (int k = 0; k < 32; k++)
        E[k] = __expf(__ldg(&trans[(size_t)row * NTAGS + lane + 32 * k]));

    // ---- Step 0: alpha_0 = trans[:,start] + u_0; replicate-publish -------
    float u_next = 0.0f;                 // lane0-only: next step's unary
    {
        const int sidx = *start_p;       // broadcast load
        float a0 = 0.0f;
        if (lane == 0) {
            a0 = __ldg(&trans[(size_t)row * NTAGS + sidx]) + __ldg(&unary[row]);
            s_a[0][w] = a0;
            s_a[1][w] = a0;              // stands in for alpha_{-1} at t=1,2
            u_next = __ldcs(&unary[(size_t)NTAGS + row]);
        }
        const float a0b = __shfl_sync(0xffffffffu, a0, 0);
        if (lane < NREP)                 // one STG: publish to all 8 replicas
            st_rlx64(&g_abR[lane][0][row], pack_av(a0b, gen * 65536u + 1u));
    }
    __syncthreads();

    // ---- Main scan: ONE barrier per step ---------------------------------
    for (int t = 1; t < TSTEPS; t++) {
        const int pb = (t - 1) & 1;
        const int b  = t & 1;

        // exp-offset from own alpha(t-2); fmax only, no MUFU on this path.
        // (reads precede this step's barrier; writers of s_a[b] this step are
        //  post-barrier, so the barrier separates them.)
        float mm = s_a[b][0];
        #pragma unroll
        for (int r = 1; r < WARPS; r++) mm = fmaxf(mm, s_a[b][r]);
        const float m = mm + 30.0f;      // covers 2 steps drift + cross-CTA spread

        const unsigned want = gen * 65536u + (unsigned)t;   // tag of step t-1
        const unsigned long long* src = g_abR[cta & (NREP - 1)][pb];

        // Detection IS the data load: poll own 4 tagged words until all fresh.
        unsigned long long q0 = ld_rlx64(src + tid);
        unsigned long long q1 = ld_rlx64(src + tid + 256);
        unsigned long long q2 = ld_rlx64(src + tid + 512);
        unsigned long long q3 = ld_rlx64(src + tid + 768);
        {
            unsigned spins = 0;
            while (((tag_of(q0) ^ want) | (tag_of(q1) ^ want) |
                    (tag_of(q2) ^ want) | (tag_of(q3) ^ want)) != 0u) {
                q0 = ld_rlx64(src + tid);       q1 = ld_rlx64(src + tid + 256);
                q2 = ld_rlx64(src + tid + 512); q3 = ld_rlx64(src + tid + 768);
                if (++spins > SPIN_CAP) { s_bail = 1; break; }
            }
        }

        float* sxb = sx[b];
        sxb[tid]       = __expf(val_of(q0) - m);
        sxb[tid + 256] = __expf(val_of(q1) - m);
        sxb[tid + 512] = __expf(val_of(q2) - m);
        sxb[tid + 768] = __expf(val_of(q3) - m);
        __syncthreads();                 // the single per-step barrier
        if (s_bail) break;

        // Row stage: warp w computes row `row` over all 1024 cols (proven R13 shape).
        float a0 = 0.f, a1 = 0.f, a2 = 0.f, a3 = 0.f;
        #pragma unroll
        for (int k = 0; k < 32; k += 4) {
            a0 = fmaf(E[k + 0], sxb[lane + 32 * (k + 0)], a0);
            a1 = fmaf(E[k + 1], sxb[lane + 32 * (k + 1)], a1);
            a2 = fmaf(E[k + 2], sxb[lane + 32 * (k + 2)], a2);
            a3 = fmaf(E[k + 3], sxb[lane + 32 * (k + 3)], a3);
        }
        float S = (a0 + a1) + (a2 + a3);
        #pragma unroll
        for (int msk = 16; msk >= 1; msk >>= 1)
            S += __shfl_xor_sync(0xffffffffu, S, msk);

        // Publish: lane 0 computes alpha; lanes 0..7 store it to the 8 replicas
        // with ONE STG.64 instruction. The tagged store is itself the signal.
        float alpha = 0.0f;
        if (lane == 0) {
            alpha = __logf(S) + m + u_next;
            s_a[b][w] = alpha;
        }
        const float alphab = __shfl_sync(0xffffffffu, alpha, 0);
        if (lane < NREP)
            st_rlx64(&g_abR[lane][b][row], pack_av(alphab, want + 1u));
        if (lane == 0) {
            const int tn = (t + 1 < TSTEPS) ? t + 1 : t;
            u_next = __ldcs(&unary[(size_t)tn * NTAGS + row]);
        }
        // next iteration's barrier provides all remaining smem ordering
    }

    // ---- Terminal logsumexp (CTA 0) --------------------------------------
    if (cta == 0) {
        const unsigned want = gen * 65536u + (unsigned)TSTEPS;  // tag of T-1
        const unsigned long long* src = g_abR[0][(TSTEPS - 1) & 1];
        unsigned long long q0 = ld_rlx64(src + tid);
        unsigned long long q1 = ld_rlx64(src + tid + 256);
        unsigned long long q2 = ld_rlx64(src + tid + 512);
        unsigned long long q3 = ld_rlx64(src + tid + 768);
        {
            unsigned vs = 0;
            while (((tag_of(q0) ^ want) | (tag_of(q1) ^ want) |
                    (tag_of(q2) ^ want) | (tag_of(q3) ^ want)) != 0u) {
                q0 = ld_rlx64(src + tid);       q1 = ld_rlx64(src + tid + 256);
                q2 = ld_rlx64(src + tid + 512); q3 = ld_rlx64(src + tid + 768);
                if (++vs > VCAP) break;
            }
        }

        const int eidx = *end_p;
        const float x0 = val_of(q0) + __ldg(&trans[(size_t)eidx * NTAGS + tid]);
        const float x1 = val_of(q1) + __ldg(&trans[(size_t)eidx * NTAGS + tid + 256]);
        const float x2 = val_of(q2) + __ldg(&trans[(size_t)eidx * NTAGS + tid + 512]);
        const float x3 = val_of(q3) + __ldg(&trans[(size_t)eidx * NTAGS + tid + 768]);

        float mx = fmaxf(fmaxf(x0, x1), fmaxf(x2, x3));
        #pragma unroll
        for (int msk = 16; msk >= 1; msk >>= 1)
            mx = fmaxf(mx, __shfl_xor_sync(0xffffffffu, mx, msk));
        float* s_red = sx[0];
        if (lane == 0) s_red[w] = mx;
        __syncthreads();
        float M = s_red[0];
        #pragma unroll
        for (int w2 = 1; w2 < WARPS; w2++) M = fmaxf(M, s_red[w2]);

        float s = __expf(x0 - M) + __expf(x1 - M) + __expf(x2 - M) + __expf(x3 - M);
        #pragma unroll
        for (int msk = 16; msk >= 1; msk >>= 1)
            s += __shfl_xor_sync(0xffffffffu, s, msk);
        if (lane == 0) s_red[16 + w] = s;
        __syncthreads();

        if (tid == 0) {
            float Ssum = s_red[16];
            #pragma unroll
            for (int w2 = 1; w2 < WARPS; w2++) Ssum += s_red[16 + w2];
            out[0] = __logf(Ssum) + M;
            g_gen = gen + 1;             // version tags for the next replay
        }
    }
}

extern "C" void kernel_launch(void* const* d_in, const int* in_sizes, int n_in,
                              void* d_out, int out_size)
{
    const float* unary = (const float*)d_in[0];   // [65536, 1024] f32
    const float* trans = (const float*)d_in[1];   // [1024, 1024]  f32
    const int*   sidx  = (const int*)d_in[2];     // scalar
    const int*   eidx  = (const int*)d_in[3];     // scalar
    float*       out   = (float*)d_out;           // scalar f32

    crf_kernel<<<NCTA, TPB>>>(unary, trans, sidx, eidx, out);
}

// round 17
// speedup vs baseline: 1.3586x; 1.0601x over previous
#include <cuda_runtime.h>

#define NTAGS    1024
#define NCTA     128
#define TPB      256
#define WARPS    8
#define NREP     8           // replicas of the P vector; CTA c polls replica c&7
#define TSTEPS   65536
#define SPIN_CAP (1u << 18)  // watchdog (~60ms worst case), unreachable normally
#define VCAP     (1u << 16)
#define MARGIN   30.0f

// Persistent device state: 8 replicas of the tagged P vector, double-buffered.
// Entry = {f32 P, u32 tag} where alpha_i(t) = log(P_i) + M_t and M_t is the
// GLOBALLY DETERMINISTIC scale M_t = alpha_{t-2}[0] + MARGIN, recomputed
// bit-identically by every CTA from data it already polls. One b64 load
// observes value+readiness atomically -> detection IS the data load.
__device__ __align__(16) unsigned long long g_abR[NREP][2][NTAGS];   // 128 KB
__device__ unsigned g_gen = 0;   // bumped once per launch (replay-safe tags)

__device__ __forceinline__ unsigned long long ld_rlx64(const unsigned long long* p) {
    unsigned long long v;
    asm volatile("ld.relaxed.gpu.global.b64 %0, [%1];" : "=l"(v) : "l"(p));
    return v;
}
__device__ __forceinline__ void st_rlx64(unsigned long long* p, unsigned long long v) {
    asm volatile("st.relaxed.gpu.global.b64 [%0], %1;" :: "l"(p), "l"(v) : "memory");
}
__device__ __forceinline__ unsigned long long pack_av(float a, unsigned tag) {
    return ((unsigned long long)tag << 32) | (unsigned long long)__float_as_uint(a);
}
__device__ __forceinline__ float    val_of(unsigned long long q) { return __uint_as_float((unsigned)q); }
__device__ __forceinline__ unsigned tag_of(unsigned long long q) { return (unsigned)(q >> 32); }

__global__ void __launch_bounds__(TPB, 1)
crf_kernel(const float* __restrict__ unary,
           const float* __restrict__ trans,
           const int*   __restrict__ start_p,
           const int*   __restrict__ end_p,
           float*       __restrict__ out)
{
    const int tid  = threadIdx.x;
    const int lane = tid & 31;
    const int w    = tid >> 5;           // 8 warps
    const int cta  = blockIdx.x;
    const int row  = cta * WARPS + w;    // this warp's tag row

    __shared__ float sx[2][NTAGS];       // raw P values, double-buffered by t&1
    __shared__ float s_P0[2];            // P[0] per parity (feeds the M recursion)
    __shared__ int   s_bail;

    const unsigned gen = g_gen;          // stream-ordered across graph replays
    // tag(step s) = gen*65536 + s + 1   (never 0, unique across replays)

    if (tid == 0) s_bail = 0;

    // ---- E row in registers: warp w owns row `row`, lane owns cols {lane+32k}
    float E[32];
    #pragma unroll
    for (int k = 0; k < 32; k++)
        E[k] = __expf(__ldg(&trans[(size_t)row * NTAGS + lane + 32 * k]));

    // ---- Step 0: alpha_0 = trans[:,start] + u_0; publish P = exp(alpha_0)
    // (scale M_0 = 0). u_next loaded by ALL lanes (same address -> broadcast).
    float u_next;
    {
        const int sidx = *start_p;       // broadcast load
        const float a0 = __ldg(&trans[(size_t)row * NTAGS + sidx]) + __ldg(&unary[row]);
        const float P0 = __expf(a0);
        if (lane < NREP)                 // one STG: publish to all 8 replicas
            st_rlx64(&g_abR[lane][0][row], pack_av(P0, gen * 65536u + 1u));
        u_next = __ldcs(&unary[(size_t)NTAGS + row]);
    }
    float M0 = 0.0f, M1 = MARGIN;        // M per parity: M_0 = 0; M_1 = MARGIN
    __syncthreads();

    // ---- Main scan: ONE barrier per step; MUFU-free critical path --------
    for (int t = 1; t < TSTEPS; t++) {
        const int pb = (t - 1) & 1;
        const int b  = t & 1;

        const unsigned want = gen * 65536u + (unsigned)t;   // tag of step t-1
        const unsigned long long* src = g_abR[cta & (NREP - 1)][pb];

        // Issue the 4 poll loads FIRST so the M/f math below hides in their flight.
        unsigned long long q0 = ld_rlx64(src + tid);
        unsigned long long q1 = ld_rlx64(src + tid + 256);
        unsigned long long q2 = ld_rlx64(src + tid + 512);
        unsigned long long q3 = ld_rlx64(src + tid + 768);

        // Global deterministic scale (identical on every CTA/warp/lane):
        //   M_t = log(P_{t-2}[0]) + M_{t-2} + MARGIN  (t>=2);  M_1 = MARGIN.
        // s_P0[b] was written at step t-1 (slot (t-2)&1 == b), bar-separated.
        const float Mref  = b ? M1 : M0;               // M_{t-2}
        const float Mprev = b ? M0 : M1;               // M_{t-1}
        const float Mt    = (t == 1) ? MARGIN
                                     : __logf(s_P0[b]) + Mref + MARGIN;
        if (b) M1 = Mt; else M0 = Mt;
        const float f = __expf(Mprev - Mt + u_next);   // publish factor (off-path)

        // Detection IS the data load: spin until all 4 words carry tag `want`.
        {
            unsigned spins = 0;
            while (((tag_of(q0) ^ want) | (tag_of(q1) ^ want) |
                    (tag_of(q2) ^ want) | (tag_of(q3) ^ want)) != 0u) {
                q0 = ld_rlx64(src + tid);       q1 = ld_rlx64(src + tid + 256);
                q2 = ld_rlx64(src + tid + 512); q3 = ld_rlx64(src + tid + 768);
                if (++spins > SPIN_CAP) { s_bail = 1; break; }
            }
        }

        if (tid == 0) s_P0[pb] = val_of(q0);   // feed the M recursion (pre-bar)

        // Stage RAW P values -- no exp, pure data movement.
        float* sxb = sx[b];
        sxb[tid]       = val_of(q0);
        sxb[tid + 256] = val_of(q1);
        sxb[tid + 512] = val_of(q2);
        sxb[tid + 768] = val_of(q3);
        __syncthreads();                 // the single per-step barrier
        if (s_bail) break;

        // Row stage: warp w computes row `row` over all 1024 cols.
        float a0 = 0.f, a1 = 0.f, a2 = 0.f, a3 = 0.f;
        #pragma unroll
        for (int k = 0; k < 32; k += 4) {
            a0 = fmaf(E[k + 0], sxb[lane + 32 * (k + 0)], a0);
            a1 = fmaf(E[k + 1], sxb[lane + 32 * (k + 1)], a1);
            a2 = fmaf(E[k + 2], sxb[lane + 32 * (k + 2)], a2);
            a3 = fmaf(E[k + 3], sxb[lane + 32 * (k + 3)], a3);
        }
        float S = (a0 + a1) + (a2 + a3);
        #pragma unroll
        for (int msk = 16; msk >= 1; msk >>= 1)
            S += __shfl_xor_sync(0xffffffffu, S, msk);

        // Publish: P_t = S * f. One FMUL then one STG.64 to all 8 replicas.
        // All lanes hold S (xor-reduce) and f, so no broadcast needed.
        const float P = S * f;
        if (lane < NREP)
            st_rlx64(&g_abR[lane][b][row], pack_av(P, want + 1u));
        {   // prefetch next unary (all lanes, same address -> broadcast)
            const int tn = (t + 1 < TSTEPS) ? t + 1 : t;
            u_next = __ldcs(&unary[(size_t)tn * NTAGS + row]);
        }
        // next iteration's barrier provides all remaining smem ordering
    }
    // After the loop, every lane holds M_{T-1} in M[(TSTEPS-1)&1] (= M1).

    // ---- Terminal logsumexp (CTA 0): alpha = log(P) + M_{T-1} ------------
    if (cta == 0) {
        const unsigned want = gen * 65536u + (unsigned)TSTEPS;  // tag of T-1
        const unsigned long long* src = g_abR[0][(TSTEPS - 1) & 1];
        unsigned long long q0 = ld_rlx64(src + tid);
        unsigned long long q1 = ld_rlx64(src + tid + 256);
        unsigned long long q2 = ld_rlx64(src + tid + 512);
        unsigned long long q3 = ld_rlx64(src + tid + 768);
        {
            unsigned vs = 0;
            while (((tag_of(q0) ^ want) | (tag_of(q1) ^ want) |
                    (tag_of(q2) ^ want) | (tag_of(q3) ^ want)) != 0u) {
                q0 = ld_rlx64(src + tid);       q1 = ld_rlx64(src + tid + 256);
                q2 = ld_rlx64(src + tid + 512); q3 = ld_rlx64(src + tid + 768);
                if (++vs > VCAP) break;
            }
        }
        const float Mlast = M1;          // M_{T-1}, tracked by every lane

        const int eidx = *end_p;
        const float x0 = __logf(val_of(q0)) + Mlast + __ldg(&trans[(size_t)eidx * NTAGS + tid]);
        const float x1 = __logf(val_of(q1)) + Mlast + __ldg(&trans[(size_t)eidx * NTAGS + tid + 256]);
        const float x2 = __logf(val_of(q2)) + Mlast + __ldg(&trans[(size_t)eidx * NTAGS + tid + 512]);
        const float x3 = __logf(val_of(q3)) + Mlast + __ldg(&trans[(size_t)eidx * NTAGS + tid + 768]);

        float mx = fmaxf(fmaxf(x0, x1), fmaxf(x2, x3));
        #pragma unroll
        for (int msk = 16; msk >= 1; msk >>= 1)
            mx = fmaxf(mx, __shfl_xor_sync(0xffffffffu, mx, msk));
        float* s_red = sx[0];
        if (lane == 0) s_red[w] = mx;
        __syncthreads();
        float M = s_red[0];
        #pragma unroll
        for (int w2 = 1; w2 < WARPS; w2++) M = fmaxf(M, s_red[w2]);

        float s = __expf(x0 - M) + __expf(x1 - M) + __expf(x2 - M) + __expf(x3 - M);
        #pragma unroll
        for (int msk = 16; msk >= 1; msk >>= 1)
            s += __shfl_xor_sync(0xffffffffu, s, msk);
        if (lane == 0) s_red[16 + w] = s;
        __syncthreads();

        if (tid == 0) {
            float Ssum = s_red[16];
            #pragma unroll
            for (int w2 = 1; w2 < WARPS; w2++) Ssum += s_red[16 + w2];
            out[0] = __logf(Ssum) + M;
            g_gen = gen + 1;             // version tags for the next replay
        }
    }
}

extern "C" void kernel_launch(void* const* d_in, const int* in_sizes, int n_in,
                              void* d_out, int out_size)
{
    const float* unary = (const float*)d_in[0];   // [65536, 1024] f32
    const float* trans = (const float*)d_in[1];   // [1024, 1024]  f32
    const int*   sidx  = (const int*)d_in[2];     // scalar
    const int*   eidx  = (const int*)d_in[3];     // scalar
    float*       out   = (float*)d_out;           // scalar f32

    crf_kernel<<<NCTA, TPB>>>(unary, trans, sidx, eidx, out);
}